// round 17
// baseline (speedup 1.0000x reference)
#include <cuda_runtime.h>
#include <math.h>
#include <float.h>
#include <stdint.h>

// Problem constants
#define B_ 8
#define T_ 512
#define D_ 256
#define S_ 64
#define P_ 1024
#define R_ 12

// Scratch (device globals — no allocation allowed)
__device__ float g_pA_hi[B_ * S_ * D_];         // tf32-rounded pooled, hi part
__device__ float g_pA_lo[B_ * S_ * D_];         // tf32 lo residual
__device__ float g_L[B_ * S_ * 2 * R_];         // [bs][h*12+r]
__device__ float g_wb_hi[R_ * D_ * D_];         // tf32 hi of W_bilinear (3 MB)
__device__ float g_wb_lo[R_ * D_ * D_];         // tf32 lo residual     (3 MB)

__device__ __forceinline__ float tf32r(float x) {
    uint32_t u;
    asm("cvt.rna.tf32.f32 %0, %1;" : "=r"(u) : "f"(x));
    return __uint_as_float(u);
}

#define MMA_TF32(C, A, Bv)                                                   \
    asm volatile(                                                            \
        "mma.sync.aligned.m16n8k8.row.col.f32.tf32.tf32.f32 "                \
        "{%0,%1,%2,%3}, {%4,%5,%6,%7}, {%8,%9}, {%0,%1,%2,%3};"              \
        : "+f"(C[0]), "+f"(C[1]), "+f"(C[2]), "+f"(C[3])                     \
        : "r"(A[0]), "r"(A[1]), "r"(A[2]), "r"(A[3]), "r"(Bv[0]), "r"(Bv[1]))

#define CP16(dst, src)                                                       \
    asm volatile("cp.async.cg.shared.global [%0], [%1], 16;"                 \
                 :: "r"(dst), "l"(src) : "memory")

// ---------------------------------------------------------------------------
// Kernel 1: ragged span max-pool + per-span linear terms (proven form,
// 4-way-unrolled max loop), emitting tf32 hi/lo split of pooled.
// ---------------------------------------------------------------------------
__global__ __launch_bounds__(256)
void pool_kernel(const float* __restrict__ enc,
                 const float* __restrict__ Wl,   // [2D, R] row-major
                 const int* __restrict__ starts,
                 const int* __restrict__ lens) {
    __shared__ float sp[D_];
    __shared__ float red[8 * 24];

    int bs  = blockIdx.x;          // b*64 + s
    int b   = bs >> 6;
    int tid = threadIdx.x;
    int warp = tid >> 5, lane = tid & 31;

    int st = starts[bs];
    int en = st + lens[bs] + 1;    // exclusive, >= st+1
    if (en > T_) en = T_;

    const float* p = enc + ((size_t)b * T_ + st) * D_ + tid;
    float m = -FLT_MAX;
    int t = st;
    for (; t + 4 <= en; t += 4) {
        float a0 = p[0];
        float a1 = p[D_];
        float a2 = p[2 * D_];
        float a3 = p[3 * D_];
        m = fmaxf(m, fmaxf(fmaxf(a0, a1), fmaxf(a2, a3)));
        p += 4 * D_;
    }
    for (; t < en; ++t) { m = fmaxf(m, *p); p += D_; }

    float hi = tf32r(m);
    g_pA_hi[bs * D_ + tid] = hi;
    g_pA_lo[bs * D_ + tid] = tf32r(m - hi);
    sp[tid] = m;
    __syncthreads();

    if (lane < 24) {
        int h = (lane >= 12);
        int r = lane - h * 12;
        const float* wp = Wl + h * (D_ * R_) + r;
        int d0 = warp * 32;
        float sum = 0.f;
#pragma unroll
        for (int dd = 0; dd < 32; ++dd) {
            int d = d0 + dd;
            sum += sp[d] * wp[d * R_];
        }
        red[warp * 24 + lane] = sum;
    }
    __syncthreads();

    if (tid < 24) {
        float s = 0.f;
#pragma unroll
        for (int wp8 = 0; wp8 < 8; ++wp8) s += red[wp8 * 24 + tid];
        g_L[bs * (2 * R_) + tid] = s;
    }
}

// ---------------------------------------------------------------------------
// Kernel 1b: split W_bilinear into tf32 hi/lo. (proven R13 form)
// ---------------------------------------------------------------------------
__global__ __launch_bounds__(256)
void split_wb_kernel(const float* __restrict__ Wb) {
    int idx = blockIdx.x * 256 + threadIdx.x;     // 0..65535
    const float4* src = (const float4*)Wb;
    float4* dhi = (float4*)g_wb_hi;
    float4* dlo = (float4*)g_wb_lo;
#pragma unroll
    for (int i = 0; i < 3; ++i) {
        int j = idx + i * 65536;
        float4 v = src[j];
        float4 h, l;
        h.x = tf32r(v.x); l.x = tf32r(v.x - h.x);
        h.y = tf32r(v.y); l.y = tf32r(v.y - h.y);
        h.z = tf32r(v.z); l.z = tf32r(v.z - h.z);
        h.w = tf32r(v.w); l.w = tf32r(v.w - h.w);
        dhi[j] = h;
        dlo[j] = l;
    }
}

// ---------------------------------------------------------------------------
// Kernel 2: FUSED bilinear kernel, one block per (b,r), 96 blocks.
// Phase 1: T1[s,e] = sum_d pooled[b,s,d]*Wb[r,d,e]   (64x256x256, 3xTF32)
//   - BK=32, depth-2 cp.async pipeline (R14-proven pattern), 85 KB stages.
//   - T1 stays in fp32 accumulators (64 regs/thread), then parked in smem.
// Phase 2: G[s,t] = sum_e T1[s,e]*pooled[b,t,e]       (64x64x256, 3xTF32)
//   - A frags = on-the-fly tf32 hi/lo split of smem T1 (identical math to
//     the previous stored split). B = pooled hi/lo, 3-stage prefetch.
// Epilogue: G tile -> smem -> fused pair-score gather (R11/R15-proven).
// ---------------------------------------------------------------------------
#define A1P 36
#define A1SZ (64 * A1P)                 // 2304 floats (per hi or lo)
#define B1P 260
#define B1SZ (32 * B1P)                 // 8320 floats
#define STG1 (2 * A1SZ + 2 * B1SZ)      // 21248 floats = 84992 B
#define T1P 260
#define T1SZ (64 * T1P)                 // 16640 floats = 66560 B
#define B2P 36
#define B2SZ (64 * B2P)                 // 2304 floats per hi/lo
#define STG2 (2 * B2SZ)                 // 4608 floats = 18432 B
#define FUSED_SMEM (2 * STG1 * 4)       // 169984 B (phase 2 fits inside)

__global__ __launch_bounds__(256)
void fused_kernel(const float* __restrict__ bias,
                  const int* __restrict__ ph,
                  const int* __restrict__ pt,
                  float* __restrict__ out) {
    extern __shared__ float smem[];

    int bid = blockIdx.x;                 // b*12 + r
    int b = bid / R_;
    int r = bid - b * R_;

    int tid = threadIdx.x;
    int wid = tid >> 5, lane = tid & 31;
    int g = lane >> 2, c = lane & 3;
    int warp_m = wid >> 2;                // 0..1
    int warp_n = wid & 3;                 // 0..3

    const float* pAhi = g_pA_hi + (size_t)b * S_ * D_;   // row s/t: +row*256
    const float* pAlo = g_pA_lo + (size_t)b * S_ * D_;
    const float* wbh  = g_wb_hi + (size_t)r * (D_ * D_);
    const float* wbl  = g_wb_lo + (size_t)r * (D_ * D_);

    unsigned sbase = (unsigned)__cvta_generic_to_shared(smem);

    // ===================== Phase 1: T1 = pooled * Wb =====================
    float acc1[2][8][4] = {};

    // Stage: [Ahi 64x36][Alo][Bhi 32x260][Blo]; 20 cp.async per thread.
    auto issue1 = [&](int s, int d0) {
        unsigned st = sbase + (unsigned)(s * STG1 * 4);
#pragma unroll
        for (int i = 0; i < 2; ++i) {
            int op = tid + i * 256;           // 0..511
            int row = op >> 3, ch = op & 7;   // A: 64 rows x 8 chunks
            unsigned da = st + (unsigned)((row * A1P + ch * 4) * 4);
            CP16(da, pAhi + (size_t)row * D_ + d0 + ch * 4);
            CP16(da + (unsigned)(A1SZ * 4), pAlo + (size_t)row * D_ + d0 + ch * 4);
        }
#pragma unroll
        for (int i = 0; i < 8; ++i) {
            int op = tid + i * 256;           // 0..2047
            int row = op >> 6, ch = op & 63;  // B: 32 rows x 64 chunks
            unsigned db = st + (unsigned)((2 * A1SZ + row * B1P + ch * 4) * 4);
            CP16(db, wbh + (size_t)(d0 + row) * D_ + ch * 4);
            CP16(db + (unsigned)(B1SZ * 4), wbl + (size_t)(d0 + row) * D_ + ch * 4);
        }
        asm volatile("cp.async.commit_group;" ::: "memory");
    };

    issue1(0, 0);
    asm volatile("cp.async.wait_group 0;" ::: "memory");
    __syncthreads();

#pragma unroll 1
    for (int it = 0; it < 8; ++it) {
        int s = it & 1;
        if (it < 7) issue1(1 - s, (it + 1) * 32);

        const float* Ah = smem + s * STG1;
        const float* Al = Ah + A1SZ;
        const float* Bh = Al + A1SZ;
        const float* Bl = Bh + B1SZ;

#pragma unroll
        for (int k8 = 0; k8 < 4; ++k8) {
            int kc = k8 * 8 + c;
            uint32_t ah[2][4], al[2][4];
#pragma unroll
            for (int mi = 0; mi < 2; ++mi) {
                int rb = warp_m * 32 + mi * 16 + g;
                ah[mi][0] = __float_as_uint(Ah[rb * A1P + kc]);
                ah[mi][1] = __float_as_uint(Ah[(rb + 8) * A1P + kc]);
                ah[mi][2] = __float_as_uint(Ah[rb * A1P + kc + 4]);
                ah[mi][3] = __float_as_uint(Ah[(rb + 8) * A1P + kc + 4]);
                al[mi][0] = __float_as_uint(Al[rb * A1P + kc]);
                al[mi][1] = __float_as_uint(Al[(rb + 8) * A1P + kc]);
                al[mi][2] = __float_as_uint(Al[rb * A1P + kc + 4]);
                al[mi][3] = __float_as_uint(Al[(rb + 8) * A1P + kc + 4]);
            }
#pragma unroll
            for (int ni = 0; ni < 8; ++ni) {
                int nb = warp_n * 64 + ni * 8 + g;
                uint32_t bh[2], bl[2];
                bh[0] = __float_as_uint(Bh[kc * B1P + nb]);
                bh[1] = __float_as_uint(Bh[(kc + 4) * B1P + nb]);
                bl[0] = __float_as_uint(Bl[kc * B1P + nb]);
                bl[1] = __float_as_uint(Bl[(kc + 4) * B1P + nb]);
#pragma unroll
                for (int mi = 0; mi < 2; ++mi) {
                    MMA_TF32(acc1[mi][ni], ah[mi], bh);
                    MMA_TF32(acc1[mi][ni], ah[mi], bl);
                    MMA_TF32(acc1[mi][ni], al[mi], bh);
                }
            }
        }

        if (it < 7) asm volatile("cp.async.wait_group 0;" ::: "memory");
        __syncthreads();
    }

    // Park T1 (fp32) in smem: rows s 0..63, pitch 260. Pipeline smem is dead.
    float* T1s = smem;
#pragma unroll
    for (int mi = 0; mi < 2; ++mi)
#pragma unroll
        for (int ni = 0; ni < 8; ++ni) {
            int row = warp_m * 32 + mi * 16 + g;
            int col = warp_n * 64 + ni * 8 + 2 * c;
            T1s[row * T1P + col]           = acc1[mi][ni][0];
            T1s[row * T1P + col + 1]       = acc1[mi][ni][1];
            T1s[(row + 8) * T1P + col]     = acc1[mi][ni][2];
            T1s[(row + 8) * T1P + col + 1] = acc1[mi][ni][3];
        }

    // ================= Phase 2: G = T1 * pooled^T =================
    float acc2[2][2][4] = {};

    // Phase-2 B stages live above T1 (float offset T1SZ), 3 stages.
    auto issue2 = [&](int s, int e0) {
        unsigned st = sbase + (unsigned)((T1SZ + s * STG2) * 4);
#pragma unroll
        for (int i = 0; i < 2; ++i) {
            int op = tid + i * 256;           // 0..511
            int row = op >> 3, ch = op & 7;   // 64 rows x 8 chunks
            unsigned db = st + (unsigned)((row * B2P + ch * 4) * 4);
            CP16(db, pAhi + (size_t)row * D_ + e0 + ch * 4);
            CP16(db + (unsigned)(B2SZ * 4), pAlo + (size_t)row * D_ + e0 + ch * 4);
        }
        asm volatile("cp.async.commit_group;" ::: "memory");
    };

    issue2(0, 0);
    issue2(1, 32);
    asm volatile("cp.async.wait_group 1;" ::: "memory");
    __syncthreads();    // also publishes T1s stores

#pragma unroll 1
    for (int it = 0; it < 8; ++it) {
        int s = it % 3;
        const float* Bh = smem + T1SZ + s * STG2;
        const float* Bl = Bh + B2SZ;

#pragma unroll
        for (int k8 = 0; k8 < 4; ++k8) {
            int kc = k8 * 8 + c;          // e within chunk base
            int ec = it * 32 + kc;        // absolute e for T1s columns
            uint32_t ah[2][4], al[2][4];
#pragma unroll
            for (int mi = 0; mi < 2; ++mi) {
                int rb = warp_m * 32 + mi * 16 + g;
                float v0 = T1s[rb * T1P + ec];
                float v1 = T1s[(rb + 8) * T1P + ec];
                float v2 = T1s[rb * T1P + ec + 4];
                float v3 = T1s[(rb + 8) * T1P + ec + 4];
                float h0 = tf32r(v0), h1 = tf32r(v1);
                float h2 = tf32r(v2), h3 = tf32r(v3);
                ah[mi][0] = __float_as_uint(h0);
                ah[mi][1] = __float_as_uint(h1);
                ah[mi][2] = __float_as_uint(h2);
                ah[mi][3] = __float_as_uint(h3);
                al[mi][0] = __float_as_uint(tf32r(v0 - h0));
                al[mi][1] = __float_as_uint(tf32r(v1 - h1));
                al[mi][2] = __float_as_uint(tf32r(v2 - h2));
                al[mi][3] = __float_as_uint(tf32r(v3 - h3));
            }
#pragma unroll
            for (int ni = 0; ni < 2; ++ni) {
                int nb = warp_n * 16 + ni * 8 + g;
                uint32_t bh[2], bl[2];
                bh[0] = __float_as_uint(Bh[nb * B2P + kc]);
                bh[1] = __float_as_uint(Bh[nb * B2P + kc + 4]);
                bl[0] = __float_as_uint(Bl[nb * B2P + kc]);
                bl[1] = __float_as_uint(Bl[nb * B2P + kc + 4]);
#pragma unroll
                for (int mi = 0; mi < 2; ++mi) {
                    MMA_TF32(acc2[mi][ni], ah[mi], bh);
                    MMA_TF32(acc2[mi][ni], ah[mi], bl);
                    MMA_TF32(acc2[mi][ni], al[mi], bh);
                }
            }
        }

        if (it + 2 < 8) {
            issue2((it + 2) % 3, (it + 2) * 32);
            asm volatile("cp.async.wait_group 1;" ::: "memory");
        } else {
            asm volatile("cp.async.wait_group 0;" ::: "memory");
        }
        __syncthreads();
    }

    // Park G tile (overwrites T1s region; all T1 reads are done), gather.
    float* sg = smem;                 // 64x64 = 16 KB
#pragma unroll
    for (int mi = 0; mi < 2; ++mi)
#pragma unroll
        for (int ni = 0; ni < 2; ++ni) {
            int row = warp_m * 32 + mi * 16 + g;
            int col = warp_n * 16 + ni * 8 + 2 * c;
            sg[row * 64 + col]           = acc2[mi][ni][0];
            sg[row * 64 + col + 1]       = acc2[mi][ni][1];
            sg[(row + 8) * 64 + col]     = acc2[mi][ni][2];
            sg[(row + 8) * 64 + col + 1] = acc2[mi][ni][3];
        }
    __syncthreads();

    // Fused pair-score gather: 1024 pairs / 256 threads = 4 each.
    float bv = bias[r];
    const float* Lb = g_L + (size_t)b * S_ * (2 * R_);
    const int* phb = ph + (b << 10);
    const int* ptb = pt + (b << 10);
#pragma unroll
    for (int i = 0; i < 4; ++i) {
        int p = tid + i * 256;
        int h = phb[p];
        int t = ptb[p];
        float sc = sg[h * 64 + t] + Lb[h * 24 + r] + Lb[t * 24 + 12 + r] + bv;
        out[(size_t)((b << 10) + p) * R_ + r] = 1.f / (1.f + __expf(-sc));
    }
}

// ---------------------------------------------------------------------------
// Launch.  Inputs in metadata order:
// 0 encoded f32 [8,512,256]   1 W_linear f32 [512,12]   2 b_linear f32 [12]
// 3 W_bilinear f32 [12,256,256]
// 4 span_starts i32 [8,64]    5 span_lens i32 [8,64]
// 6 pair_head i32 [8,1024]    7 pair_tail i32 [8,1024]
// Output f32 [8,1024,12].
// ---------------------------------------------------------------------------
extern "C" void kernel_launch(void* const* d_in, const int* in_sizes, int n_in,
                              void* d_out, int out_size) {
    const float* enc = (const float*)d_in[0];
    const float* Wl  = (const float*)d_in[1];
    const float* bl  = (const float*)d_in[2];
    const float* Wb  = (const float*)d_in[3];
    const int* sst   = (const int*)d_in[4];
    const int* sln   = (const int*)d_in[5];
    const int* ph    = (const int*)d_in[6];
    const int* pt    = (const int*)d_in[7];
    float* out = (float*)d_out;

    cudaFuncSetAttribute(fused_kernel,
                         cudaFuncAttributeMaxDynamicSharedMemorySize,
                         FUSED_SMEM);

    pool_kernel<<<B_ * S_, 256>>>(enc, Wl, sst, sln);
    split_wb_kernel<<<256, 256>>>(Wb);
    fused_kernel<<<B_ * R_, 256, FUSED_SMEM>>>(bl, ph, pt, out);
}